// round 13
// baseline (speedup 1.0000x reference)
#include <cuda_runtime.h>
#include <cuda_fp16.h>
#include <cstdint>
#include <math.h>

#define B_ 2
#define H_ 16
#define S_ 2048
#define E_ 64
#define NTOK (B_*S_*H_)
#define BM 128
#define BN 64
#define NT_ (S_/BN)
#define LOG2E 1.4426950408889634f

// fp16 split levels of projected Q,K,V in [B,H,S,E] layout (Q pre-scaled by 8*log2e)
__device__ __half g_q0[B_*H_*S_*E_];
__device__ __half g_q1[B_*H_*S_*E_];
__device__ __half g_k0[B_*H_*S_*E_];
__device__ __half g_k1[B_*H_*S_*E_];
__device__ __half g_v0[B_*H_*S_*E_];
__device__ __half g_v1[B_*H_*S_*E_];

// ---------------- helpers ----------------
__device__ __forceinline__ uint32_t smem_u32(const void* p) {
    uint32_t a;
    asm("{ .reg .u64 t; cvta.to.shared.u64 t, %1; cvt.u32.u64 %0, t; }" : "=r"(a) : "l"(p));
    return a;
}
__device__ __forceinline__ void cpasync16(uint32_t dst, const void* src) {
    asm volatile("cp.async.cg.shared.global [%0], [%1], 16;" :: "r"(dst), "l"(src));
}
#define CP_COMMIT() asm volatile("cp.async.commit_group;" ::: "memory")
#define CP_WAIT1()  asm volatile("cp.async.wait_group 1;" ::: "memory")
#define CP_WAIT0()  asm volatile("cp.async.wait_group 0;" ::: "memory")

__device__ __forceinline__ void ldsm_x4(uint32_t& r0, uint32_t& r1, uint32_t& r2,
                                        uint32_t& r3, uint32_t a) {
    asm volatile("ldmatrix.sync.aligned.m8n8.x4.shared.b16 {%0,%1,%2,%3}, [%4];"
                 : "=r"(r0), "=r"(r1), "=r"(r2), "=r"(r3) : "r"(a));
}
__device__ __forceinline__ void ldsm_x4t(uint32_t& r0, uint32_t& r1, uint32_t& r2,
                                         uint32_t& r3, uint32_t a) {
    asm volatile("ldmatrix.sync.aligned.m8n8.x4.trans.shared.b16 {%0,%1,%2,%3}, [%4];"
                 : "=r"(r0), "=r"(r1), "=r"(r2), "=r"(r3) : "r"(a));
}
__device__ __forceinline__ void mma_f16(float* c, const uint32_t* a,
                                        uint32_t b0, uint32_t b1) {
    asm volatile("mma.sync.aligned.m16n8k16.row.col.f32.f16.f16.f32 "
                 "{%0,%1,%2,%3}, {%4,%5,%6,%7}, {%8,%9}, {%0,%1,%2,%3};"
                 : "+f"(c[0]), "+f"(c[1]), "+f"(c[2]), "+f"(c[3])
                 : "r"(a[0]), "r"(a[1]), "r"(a[2]), "r"(a[3]), "r"(b0), "r"(b1));
}
__device__ __forceinline__ uint32_t packh2(float x, float y) {
    __half2 t = __floats2half2_rn(x, y);
    return *(uint32_t*)&t;
}

// ---------------- exact JAX threefry, key=(0,42), partitionable ----------------
__device__ __forceinline__ uint32_t threefry_bits_42(uint32_t c1) {
    const uint32_t ks1 = 42u, ks2 = 0x1BD11BDAu ^ 42u;
    uint32_t x0 = 0u, x1 = c1 + ks1;
#define TF_R(r) { x0 += x1; x1 = __funnelshift_l(x1, x1, (r)); x1 ^= x0; }
    TF_R(13) TF_R(15) TF_R(26) TF_R(6)
    x0 += ks1; x1 += ks2 + 1u;
    TF_R(17) TF_R(29) TF_R(16) TF_R(24)
    x0 += ks2; x1 += 2u;
    TF_R(13) TF_R(15) TF_R(26) TF_R(6)
    x1 += ks1 + 3u;
    TF_R(17) TF_R(29) TF_R(16) TF_R(24)
    x0 += ks1; x1 += ks2 + 4u;
    TF_R(13) TF_R(15) TF_R(26) TF_R(6)
    x0 += ks2; x1 += 5u;
#undef TF_R
    return x0 ^ x1;
}
__device__ __forceinline__ float jax_uniform(uint32_t bits) {
    return __uint_as_float((bits >> 9) | 0x3f800000u) - 1.0f;
}

// ---------------- fused projection (grid.y selects q/k/v), fp16 2-level split ----
__global__ __launch_bounds__(256) void proj_kernel(
    const float* __restrict__ xq, const float* __restrict__ xk,
    const float* __restrict__ xv,
    const float* __restrict__ Wq, const float* __restrict__ Wk,
    const float* __restrict__ Wv,
    const float* __restrict__ bq, const float* __restrict__ bk,
    const float* __restrict__ bv,
    const float* __restrict__ inv_scale)
{
    __shared__ float Xs[64][65];
    __shared__ float Ws[64][65];
    __shared__ float bs[64];
    const int which = blockIdx.y;
    const float* x = (which == 0) ? xq : (which == 1) ? xk : xv;
    const float* W = (which == 0) ? Wq : (which == 1) ? Wk : Wv;
    const float* bias = (which == 0) ? bq : (which == 1) ? bk : bv;
    __half* o0 = (which == 0) ? g_q0 : (which == 1) ? g_k0 : g_v0;
    __half* o1 = (which == 0) ? g_q1 : (which == 1) ? g_k1 : g_v1;
    // Q is pre-scaled so that QK^T emerges in log2 domain: q *= log2e / inv_scale
    const float scl = (which == 0) ? (LOG2E / inv_scale[0]) : 1.0f;

    const int tid = threadIdx.x;
    const int n0  = blockIdx.x * 64;
    #pragma unroll
    for (int it = 0; it < 4; ++it) {
        int elem = tid * 4 + it * 1024;
        int r = elem >> 6, c = elem & 63;
        float4 w4 = *(const float4*)(W + elem);
        Ws[r][c] = w4.x; Ws[r][c+1] = w4.y; Ws[r][c+2] = w4.z; Ws[r][c+3] = w4.w;
        float4 x4 = *(const float4*)(x + (size_t)n0 * 64 + elem);
        Xs[r][c] = x4.x; Xs[r][c+1] = x4.y; Xs[r][c+2] = x4.z; Xs[r][c+3] = x4.w;
    }
    if (tid < 64) bs[tid] = bias[tid];
    __syncthreads();
    const int tx = tid & 15, ty = tid >> 4;
    float acc[4][4] = {};
    #pragma unroll 8
    for (int d = 0; d < 64; ++d) {
        float a[4], b[4];
        #pragma unroll
        for (int i = 0; i < 4; ++i) a[i] = Xs[ty*4+i][d];
        #pragma unroll
        for (int j = 0; j < 4; ++j) b[j] = Ws[tx*4+j][d];
        #pragma unroll
        for (int i = 0; i < 4; ++i)
            #pragma unroll
            for (int j = 0; j < 4; ++j)
                acc[i][j] = fmaf(a[i], b[j], acc[i][j]);
    }
    #pragma unroll
    for (int i = 0; i < 4; ++i) {
        int n = n0 + ty*4 + i;
        int b_ = n >> 15, rem = n & 32767, s = rem >> 4, h = n & 15;
        size_t off = ((((size_t)b_ * H_ + h) * S_ + s) << 6);
        #pragma unroll
        for (int j = 0; j < 4; ++j) {
            int e = tx*4 + j;
            float v = (acc[i][j] + bs[e]) * scl;
            __half h0 = __float2half_rn(v);
            o0[off + e] = h0;
            o1[off + e] = __float2half_rn(v - __half2float(h0));
        }
    }
}

// ---------------- mma.sync fp16 flash attention, cp.async + mask-in-accum ----------------
#define SQ0 0
#define SQ1 16384
#define SKV 32768
#define KVB 32768
#define SMEM_TOT 98304
__device__ __forceinline__ int swb(int r, int c8) {
    return r * 128 + ((c8 ^ (r & 7)) << 4);
}

__global__ __launch_bounds__(256, 2) void attn_kernel(
    const float* __restrict__ mask,
    float* __restrict__ out)
{
    extern __shared__ char smem[];
    const uint32_t sb = smem_u32(smem);
    const int tid = threadIdx.x, warp = tid >> 5, lane = tid & 31;
    const int s0 = blockIdx.x * BM, h = blockIdx.y, b = blockIdx.z;
    const int bh = b * H_ + h;
    const size_t kplane = (size_t)bh * S_;

    // prologue: stage Q (2 levels) + KV tile 0 via cp.async
    const size_t qrow = (size_t)bh * S_ + s0;
    for (int c = tid; c < 128 * 8; c += 256) {
        int r = c >> 3, c8 = c & 7;
        size_t ge = ((qrow + r) << 6) + (c8 << 3);
        int so = swb(r, c8);
        cpasync16(sb + SQ0 + so, g_q0 + ge);
        cpasync16(sb + SQ1 + so, g_q1 + ge);
    }
    for (int c = tid; c < 64 * 8; c += 256) {
        int r = c >> 3, c8 = c & 7;
        size_t ge = ((kplane + r) << 6) + (c8 << 3);
        int so = swb(r, c8);
        cpasync16(sb + SKV + 0     + so, g_k0 + ge);
        cpasync16(sb + SKV + 8192  + so, g_k1 + ge);
        cpasync16(sb + SKV + 16384 + so, g_v0 + ge);
        cpasync16(sb + SKV + 24576 + so, g_v1 + ge);
    }
    CP_COMMIT();

    const int qr = lane >> 2;
    const int qc = (lane & 3) << 1;
    const int rg0 = s0 + warp * 16 + qr;
    const int rg1 = rg0 + 8;
    const float* mrow0 = mask + ((size_t)b * S_ + rg0) * S_;
    const float* mrow1 = mask + ((size_t)b * S_ + rg1) * S_;
    const uint32_t cb0 = ((uint32_t)bh * S_ + (uint32_t)rg0) * S_;
    const uint32_t cb1 = ((uint32_t)bh * S_ + (uint32_t)rg1) * S_;

    float m0 = -INFINITY, m1 = -INFINITY, Z0 = 0.0f, Z1 = 0.0f;
    float Oa[8][4];
    #pragma unroll
    for (int d = 0; d < 8; ++d)
        #pragma unroll
        for (int j = 0; j < 4; ++j) Oa[d][j] = 0.0f;

    for (int it = 0; it < NT_; ++it) {
        const int t0 = it * BN;
        if (it + 1 < NT_) {
            const uint32_t nb = sb + SKV + (uint32_t)(((it + 1) & 1) * KVB);
            const size_t koff = kplane + (size_t)(t0 + BN);
            for (int c = tid; c < 64 * 8; c += 256) {
                int r = c >> 3, c8 = c & 7;
                size_t ge = ((koff + r) << 6) + (c8 << 3);
                int so = swb(r, c8);
                cpasync16(nb + 0     + so, g_k0 + ge);
                cpasync16(nb + 8192  + so, g_k1 + ge);
                cpasync16(nb + 16384 + so, g_v0 + ge);
                cpasync16(nb + 24576 + so, g_v1 + ge);
            }
            CP_COMMIT();
            CP_WAIT1();
        } else {
            CP_WAIT0();
        }
        __syncthreads();
        const uint32_t kb = sb + SKV + (uint32_t)((it & 1) * KVB);

        // ---- init accumulators with mask*log2e (LDGs hidden behind QK MMAs) ----
        float sacc[8][4];
        #pragma unroll
        for (int nt = 0; nt < 8; ++nt) {
            float2 mk0 = *(const float2*)(mrow0 + t0 + nt * 8 + qc);
            float2 mk1 = *(const float2*)(mrow1 + t0 + nt * 8 + qc);
            sacc[nt][0] = mk0.x * LOG2E;
            sacc[nt][1] = mk0.y * LOG2E;
            sacc[nt][2] = mk1.x * LOG2E;
            sacc[nt][3] = mk1.y * LOG2E;
        }

        // ---- QK^T: fp16 2-level, 3 terms; Q pre-scaled -> scores in log2 domain ----
        #pragma unroll
        for (int ks = 0; ks < 4; ++ks) {
            const int lr  = warp * 16 + (lane & 7) + ((lane >> 3) & 1) * 8;
            const int lc8 = 2 * ks + (lane >> 4);
            const uint32_t aoff = (uint32_t)swb(lr, lc8);
            uint32_t aH[4], aM[4];
            ldsm_x4(aH[0], aH[1], aH[2], aH[3], sb + SQ0 + aoff);
            ldsm_x4(aM[0], aM[1], aM[2], aM[3], sb + SQ1 + aoff);
            const int br  = (lane & 7) + ((lane >> 4) << 3);
            const int bc8 = 2 * ks + ((lane >> 3) & 1);
            #pragma unroll
            for (int np = 0; np < 4; ++np) {
                const uint32_t boff = (uint32_t)swb(np * 16 + br, bc8);
                uint32_t bh4[4], bm4[4];
                ldsm_x4(bh4[0], bh4[1], bh4[2], bh4[3], kb + boff);
                ldsm_x4(bm4[0], bm4[1], bm4[2], bm4[3], kb + 8192 + boff);
                mma_f16(sacc[2*np],   aH, bh4[0], bh4[1]);
                mma_f16(sacc[2*np],   aH, bm4[0], bm4[1]);
                mma_f16(sacc[2*np],   aM, bh4[0], bh4[1]);
                mma_f16(sacc[2*np+1], aH, bh4[2], bh4[3]);
                mma_f16(sacc[2*np+1], aH, bm4[2], bm4[3]);
                mma_f16(sacc[2*np+1], aM, bh4[2], bh4[3]);
            }
        }

        // ---- tile row max (scores already scaled+masked) ----
        float tm0 = -INFINITY, tm1 = -INFINITY;
        #pragma unroll
        for (int nt = 0; nt < 8; ++nt) {
            tm0 = fmaxf(tm0, fmaxf(sacc[nt][0], sacc[nt][1]));
            tm1 = fmaxf(tm1, fmaxf(sacc[nt][2], sacc[nt][3]));
        }
        tm0 = fmaxf(tm0, __shfl_xor_sync(0xffffffffu, tm0, 1));
        tm0 = fmaxf(tm0, __shfl_xor_sync(0xffffffffu, tm0, 2));
        tm1 = fmaxf(tm1, __shfl_xor_sync(0xffffffffu, tm1, 1));
        tm1 = fmaxf(tm1, __shfl_xor_sync(0xffffffffu, tm1, 2));
        const float mn0 = fmaxf(m0, tm0), mn1 = fmaxf(m1, tm1);
        const float f0 = exp2f(m0 - mn0), f1 = exp2f(m1 - mn1);
        m0 = mn0; m1 = mn1;

        // ---- exp2 + gated exact dropout ----
        float zs0 = 0.0f, zs1 = 0.0f;
        #pragma unroll
        for (int nt = 0; nt < 8; ++nt) {
            const uint32_t colb = (uint32_t)(t0 + nt * 8 + qc);
            #pragma unroll
            for (int j = 0; j < 2; ++j) {
                float p = exp2f(sacc[nt][j] - mn0);
                zs0 += p;
                if (p >= 1e-10f) {
                    uint32_t bits = threefry_bits_42(cb0 + colb + (uint32_t)j);
                    if (!(jax_uniform(bits) < 0.9f)) p = 0.0f;
                }
                sacc[nt][j] = p;
            }
            #pragma unroll
            for (int j = 0; j < 2; ++j) {
                float p = exp2f(sacc[nt][2 + j] - mn1);
                zs1 += p;
                if (p >= 1e-10f) {
                    uint32_t bits = threefry_bits_42(cb1 + colb + (uint32_t)j);
                    if (!(jax_uniform(bits) < 0.9f)) p = 0.0f;
                }
                sacc[nt][2 + j] = p;
            }
        }
        zs0 += __shfl_xor_sync(0xffffffffu, zs0, 1);
        zs0 += __shfl_xor_sync(0xffffffffu, zs0, 2);
        zs1 += __shfl_xor_sync(0xffffffffu, zs1, 1);
        zs1 += __shfl_xor_sync(0xffffffffu, zs1, 2);
        Z0 = Z0 * f0 + zs0;
        Z1 = Z1 * f1 + zs1;

        // ---- rescale O (skip when f == 1 for both halves) ----
        if (f0 != 1.0f || f1 != 1.0f) {
            #pragma unroll
            for (int d = 0; d < 8; ++d) {
                Oa[d][0] *= f0; Oa[d][1] *= f0;
                Oa[d][2] *= f1; Oa[d][3] *= f1;
            }
        }

        // ---- PV: fp16 2-level P from regs, V x4t from smem ----
        #pragma unroll
        for (int ks = 0; ks < 4; ++ks) {
            uint32_t AH[4], AL[4];
            #pragma unroll
            for (int half = 0; half < 2; ++half) {
                const int nt = 2 * ks + half;
                float pA = sacc[nt][0], pB = sacc[nt][1];
                float pC = sacc[nt][2], pD = sacc[nt][3];
                __half2 hAB = __floats2half2_rn(pA, pB);
                __half2 hCD = __floats2half2_rn(pC, pD);
                AH[half * 2 + 0] = *(uint32_t*)&hAB;
                AH[half * 2 + 1] = *(uint32_t*)&hCD;
                float lA = pA - __half2float(__low2half(hAB));
                float lB = pB - __half2float(__high2half(hAB));
                float lC = pC - __half2float(__low2half(hCD));
                float lD = pD - __half2float(__high2half(hCD));
                AL[half * 2 + 0] = packh2(lA, lB);
                AL[half * 2 + 1] = packh2(lC, lD);
            }
            const int vr = 16 * ks + (lane & 15);
            #pragma unroll
            for (int dp = 0; dp < 4; ++dp) {
                const int vc8 = 2 * dp + (lane >> 4);
                const uint32_t voff = (uint32_t)swb(vr, vc8);
                uint32_t vh4[4], vl4[4];
                ldsm_x4t(vh4[0], vh4[1], vh4[2], vh4[3], kb + 16384 + voff);
                ldsm_x4t(vl4[0], vl4[1], vl4[2], vl4[3], kb + 24576 + voff);
                mma_f16(Oa[2*dp],   AH, vh4[0], vh4[1]);
                mma_f16(Oa[2*dp],   AH, vl4[0], vl4[1]);
                mma_f16(Oa[2*dp],   AL, vh4[0], vh4[1]);
                mma_f16(Oa[2*dp+1], AH, vh4[2], vh4[3]);
                mma_f16(Oa[2*dp+1], AH, vl4[2], vl4[3]);
                mma_f16(Oa[2*dp+1], AL, vh4[2], vh4[3]);
            }
        }
        __syncthreads();
    }

    // ---- epilogue ----
    const float iz0 = 1.0f / (Z0 * 0.9f);
    const float iz1 = 1.0f / (Z1 * 0.9f);
    float* orow0 = out + (((size_t)bh * S_ + rg0) << 6);
    float* orow1 = out + (((size_t)bh * S_ + rg1) << 6);
    #pragma unroll
    for (int dt = 0; dt < 8; ++dt) {
        float2 w0 = make_float2(Oa[dt][0] * iz0, Oa[dt][1] * iz0);
        float2 w1 = make_float2(Oa[dt][2] * iz1, Oa[dt][3] * iz1);
        *(float2*)(orow0 + dt * 8 + qc) = w0;
        *(float2*)(orow1 + dt * 8 + qc) = w1;
    }
}

// ---------------------------------------------------------------------------
extern "C" void kernel_launch(void* const* d_in, const int* in_sizes, int n_in,
                              void* d_out, int out_size)
{
    const float* query     = (const float*)d_in[0];
    const float* key       = (const float*)d_in[1];
    const float* value     = (const float*)d_in[2];
    const float* attn_mask = (const float*)d_in[3];
    const float* inv_scale = (const float*)d_in[4];
    const float* Wq = (const float*)d_in[5];
    const float* bq = (const float*)d_in[6];
    const float* Wk = (const float*)d_in[7];
    const float* bk = (const float*)d_in[8];
    const float* Wv = (const float*)d_in[9];
    const float* bv = (const float*)d_in[10];
    float* out = (float*)d_out;

    dim3 pgrid(NTOK / 64, 3);
    proj_kernel<<<pgrid, 256>>>(query, key, value, Wq, Wk, Wv, bq, bk, bv,
                                inv_scale);

    cudaFuncSetAttribute(attn_kernel,
                         cudaFuncAttributeMaxDynamicSharedMemorySize, SMEM_TOT);
    dim3 grid(S_ / BM, H_, B_);
    attn_kernel<<<grid, 256, SMEM_TOT>>>(attn_mask, out);
}

// round 14
// speedup vs baseline: 1.0743x; 1.0743x over previous
#include <cuda_runtime.h>
#include <cuda_fp16.h>
#include <cstdint>
#include <math.h>

#define B_ 2
#define H_ 16
#define S_ 2048
#define E_ 64
#define NTOK (B_*S_*H_)
#define BM 128
#define BN 64
#define NT_ (S_/BN)
#define LOG2E 1.4426950408889634f

// fp16 split levels of projected Q,K,V in [B,H,S,E] layout (Q pre-scaled by 8*log2e)
__device__ __half g_q0[B_*H_*S_*E_];
__device__ __half g_q1[B_*H_*S_*E_];
__device__ __half g_k0[B_*H_*S_*E_];
__device__ __half g_k1[B_*H_*S_*E_];
__device__ __half g_v0[B_*H_*S_*E_];
__device__ __half g_v1[B_*H_*S_*E_];

// ---------------- helpers ----------------
__device__ __forceinline__ uint32_t smem_u32(const void* p) {
    uint32_t a;
    asm("{ .reg .u64 t; cvta.to.shared.u64 t, %1; cvt.u32.u64 %0, t; }" : "=r"(a) : "l"(p));
    return a;
}
__device__ __forceinline__ void cpasync16(uint32_t dst, const void* src) {
    asm volatile("cp.async.cg.shared.global [%0], [%1], 16;" :: "r"(dst), "l"(src));
}
#define CP_COMMIT() asm volatile("cp.async.commit_group;" ::: "memory")
#define CP_WAIT1()  asm volatile("cp.async.wait_group 1;" ::: "memory")
#define CP_WAIT0()  asm volatile("cp.async.wait_group 0;" ::: "memory")

__device__ __forceinline__ void ldsm_x4(uint32_t& r0, uint32_t& r1, uint32_t& r2,
                                        uint32_t& r3, uint32_t a) {
    asm volatile("ldmatrix.sync.aligned.m8n8.x4.shared.b16 {%0,%1,%2,%3}, [%4];"
                 : "=r"(r0), "=r"(r1), "=r"(r2), "=r"(r3) : "r"(a));
}
__device__ __forceinline__ void ldsm_x4t(uint32_t& r0, uint32_t& r1, uint32_t& r2,
                                         uint32_t& r3, uint32_t a) {
    asm volatile("ldmatrix.sync.aligned.m8n8.x4.trans.shared.b16 {%0,%1,%2,%3}, [%4];"
                 : "=r"(r0), "=r"(r1), "=r"(r2), "=r"(r3) : "r"(a));
}
__device__ __forceinline__ void mma_f16(float* c, const uint32_t* a,
                                        uint32_t b0, uint32_t b1) {
    asm volatile("mma.sync.aligned.m16n8k16.row.col.f32.f16.f16.f32 "
                 "{%0,%1,%2,%3}, {%4,%5,%6,%7}, {%8,%9}, {%0,%1,%2,%3};"
                 : "+f"(c[0]), "+f"(c[1]), "+f"(c[2]), "+f"(c[3])
                 : "r"(a[0]), "r"(a[1]), "r"(a[2]), "r"(a[3]), "r"(b0), "r"(b1));
}
__device__ __forceinline__ uint32_t packh2(float x, float y) {
    __half2 t = __floats2half2_rn(x, y);
    return *(uint32_t*)&t;
}

// ---------------- exact JAX threefry, key=(0,42), partitionable ----------------
__device__ __forceinline__ uint32_t threefry_bits_42(uint32_t c1) {
    const uint32_t ks1 = 42u, ks2 = 0x1BD11BDAu ^ 42u;
    uint32_t x0 = 0u, x1 = c1 + ks1;
#define TF_R(r) { x0 += x1; x1 = __funnelshift_l(x1, x1, (r)); x1 ^= x0; }
    TF_R(13) TF_R(15) TF_R(26) TF_R(6)
    x0 += ks1; x1 += ks2 + 1u;
    TF_R(17) TF_R(29) TF_R(16) TF_R(24)
    x0 += ks2; x1 += 2u;
    TF_R(13) TF_R(15) TF_R(26) TF_R(6)
    x1 += ks1 + 3u;
    TF_R(17) TF_R(29) TF_R(16) TF_R(24)
    x0 += ks1; x1 += ks2 + 4u;
    TF_R(13) TF_R(15) TF_R(26) TF_R(6)
    x0 += ks2; x1 += 5u;
#undef TF_R
    return x0 ^ x1;
}
__device__ __forceinline__ float jax_uniform(uint32_t bits) {
    return __uint_as_float((bits >> 9) | 0x3f800000u) - 1.0f;
}

// ---------------- fused projection (grid.y selects q/k/v), fp16 2-level split ----
__global__ __launch_bounds__(256) void proj_kernel(
    const float* __restrict__ xq, const float* __restrict__ xk,
    const float* __restrict__ xv,
    const float* __restrict__ Wq, const float* __restrict__ Wk,
    const float* __restrict__ Wv,
    const float* __restrict__ bq, const float* __restrict__ bk,
    const float* __restrict__ bv,
    const float* __restrict__ inv_scale)
{
    __shared__ float Xs[64][65];
    __shared__ float Ws[64][65];
    __shared__ float bs[64];
    const int which = blockIdx.y;
    const float* x = (which == 0) ? xq : (which == 1) ? xk : xv;
    const float* W = (which == 0) ? Wq : (which == 1) ? Wk : Wv;
    const float* bias = (which == 0) ? bq : (which == 1) ? bk : bv;
    __half* o0 = (which == 0) ? g_q0 : (which == 1) ? g_k0 : g_v0;
    __half* o1 = (which == 0) ? g_q1 : (which == 1) ? g_k1 : g_v1;
    // Q pre-scaled so QK^T emerges in log2 domain: q *= log2e / inv_scale
    const float scl = (which == 0) ? (LOG2E / inv_scale[0]) : 1.0f;

    const int tid = threadIdx.x;
    const int n0  = blockIdx.x * 64;
    #pragma unroll
    for (int it = 0; it < 4; ++it) {
        int elem = tid * 4 + it * 1024;
        int r = elem >> 6, c = elem & 63;
        float4 w4 = *(const float4*)(W + elem);
        Ws[r][c] = w4.x; Ws[r][c+1] = w4.y; Ws[r][c+2] = w4.z; Ws[r][c+3] = w4.w;
        float4 x4 = *(const float4*)(x + (size_t)n0 * 64 + elem);
        Xs[r][c] = x4.x; Xs[r][c+1] = x4.y; Xs[r][c+2] = x4.z; Xs[r][c+3] = x4.w;
    }
    if (tid < 64) bs[tid] = bias[tid];
    __syncthreads();
    const int tx = tid & 15, ty = tid >> 4;
    float acc[4][4] = {};
    #pragma unroll 8
    for (int d = 0; d < 64; ++d) {
        float a[4], b[4];
        #pragma unroll
        for (int i = 0; i < 4; ++i) a[i] = Xs[ty*4+i][d];
        #pragma unroll
        for (int j = 0; j < 4; ++j) b[j] = Ws[tx*4+j][d];
        #pragma unroll
        for (int i = 0; i < 4; ++i)
            #pragma unroll
            for (int j = 0; j < 4; ++j)
                acc[i][j] = fmaf(a[i], b[j], acc[i][j]);
    }
    #pragma unroll
    for (int i = 0; i < 4; ++i) {
        int n = n0 + ty*4 + i;
        int b_ = n >> 15, rem = n & 32767, s = rem >> 4, h = n & 15;
        size_t off = ((((size_t)b_ * H_ + h) * S_ + s) << 6);
        #pragma unroll
        for (int j = 0; j < 4; ++j) {
            int e = tx*4 + j;
            float v = (acc[i][j] + bs[e]) * scl;
            __half h0 = __float2half_rn(v);
            o0[off + e] = h0;
            o1[off + e] = __float2half_rn(v - __half2float(h0));
        }
    }
}

// ---------------- mma.sync fp16 flash attention, cp.async pipelined ----------------
#define SQ0 0
#define SQ1 16384
#define SKV 32768
#define KVB 32768
#define SMEM_TOT 98304
__device__ __forceinline__ int swb(int r, int c8) {
    return r * 128 + ((c8 ^ (r & 7)) << 4);
}

__global__ __launch_bounds__(256, 2) void attn_kernel(
    const float* __restrict__ mask,
    float* __restrict__ out)
{
    extern __shared__ char smem[];
    const uint32_t sb = smem_u32(smem);
    const int tid = threadIdx.x, warp = tid >> 5, lane = tid & 31;
    const int s0 = blockIdx.x * BM, h = blockIdx.y, b = blockIdx.z;
    const int bh = b * H_ + h;
    const size_t kplane = (size_t)bh * S_;

    // prologue: stage Q (2 levels) + KV tile 0 via cp.async
    const size_t qrow = (size_t)bh * S_ + s0;
    for (int c = tid; c < 128 * 8; c += 256) {
        int r = c >> 3, c8 = c & 7;
        size_t ge = ((qrow + r) << 6) + (c8 << 3);
        int so = swb(r, c8);
        cpasync16(sb + SQ0 + so, g_q0 + ge);
        cpasync16(sb + SQ1 + so, g_q1 + ge);
    }
    for (int c = tid; c < 64 * 8; c += 256) {
        int r = c >> 3, c8 = c & 7;
        size_t ge = ((kplane + r) << 6) + (c8 << 3);
        int so = swb(r, c8);
        cpasync16(sb + SKV + 0     + so, g_k0 + ge);
        cpasync16(sb + SKV + 8192  + so, g_k1 + ge);
        cpasync16(sb + SKV + 16384 + so, g_v0 + ge);
        cpasync16(sb + SKV + 24576 + so, g_v1 + ge);
    }
    CP_COMMIT();

    const int qr = lane >> 2;
    const int qc = (lane & 3) << 1;
    const int rg0 = s0 + warp * 16 + qr;
    const int rg1 = rg0 + 8;
    const float* mrow0 = mask + ((size_t)b * S_ + rg0) * S_;
    const float* mrow1 = mask + ((size_t)b * S_ + rg1) * S_;
    const uint32_t cb0 = ((uint32_t)bh * S_ + (uint32_t)rg0) * S_;
    const uint32_t cb1 = ((uint32_t)bh * S_ + (uint32_t)rg1) * S_;

    float m0 = -INFINITY, m1 = -INFINITY, Z0 = 0.0f, Z1 = 0.0f;
    float Oa[8][4];
    #pragma unroll
    for (int d = 0; d < 8; ++d)
        #pragma unroll
        for (int j = 0; j < 4; ++j) Oa[d][j] = 0.0f;

    for (int it = 0; it < NT_; ++it) {
        const int t0 = it * BN;
        if (it + 1 < NT_) {
            const uint32_t nb = sb + SKV + (uint32_t)(((it + 1) & 1) * KVB);
            const size_t koff = kplane + (size_t)(t0 + BN);
            for (int c = tid; c < 64 * 8; c += 256) {
                int r = c >> 3, c8 = c & 7;
                size_t ge = ((koff + r) << 6) + (c8 << 3);
                int so = swb(r, c8);
                cpasync16(nb + 0     + so, g_k0 + ge);
                cpasync16(nb + 8192  + so, g_k1 + ge);
                cpasync16(nb + 16384 + so, g_v0 + ge);
                cpasync16(nb + 24576 + so, g_v1 + ge);
            }
            CP_COMMIT();
            CP_WAIT1();
        } else {
            CP_WAIT0();
        }
        __syncthreads();
        const uint32_t kb = sb + SKV + (uint32_t)((it & 1) * KVB);

        // ---- QK^T: fp16 2-level, 3 terms; Q pre-scaled -> log2-domain scores ----
        float sacc[8][4];
        #pragma unroll
        for (int nt = 0; nt < 8; ++nt)
            #pragma unroll
            for (int j = 0; j < 4; ++j) sacc[nt][j] = 0.0f;

        #pragma unroll
        for (int ks = 0; ks < 4; ++ks) {
            const int lr  = warp * 16 + (lane & 7) + ((lane >> 3) & 1) * 8;
            const int lc8 = 2 * ks + (lane >> 4);
            const uint32_t aoff = (uint32_t)swb(lr, lc8);
            uint32_t aH[4], aM[4];
            ldsm_x4(aH[0], aH[1], aH[2], aH[3], sb + SQ0 + aoff);
            ldsm_x4(aM[0], aM[1], aM[2], aM[3], sb + SQ1 + aoff);
            const int br  = (lane & 7) + ((lane >> 4) << 3);
            const int bc8 = 2 * ks + ((lane >> 3) & 1);
            #pragma unroll
            for (int np = 0; np < 4; ++np) {
                const uint32_t boff = (uint32_t)swb(np * 16 + br, bc8);
                uint32_t bh4[4], bm4[4];
                ldsm_x4(bh4[0], bh4[1], bh4[2], bh4[3], kb + boff);
                ldsm_x4(bm4[0], bm4[1], bm4[2], bm4[3], kb + 8192 + boff);
                mma_f16(sacc[2*np],   aH, bh4[0], bh4[1]);
                mma_f16(sacc[2*np],   aH, bm4[0], bm4[1]);
                mma_f16(sacc[2*np],   aM, bh4[0], bh4[1]);
                mma_f16(sacc[2*np+1], aH, bh4[2], bh4[3]);
                mma_f16(sacc[2*np+1], aH, bm4[2], bm4[3]);
                mma_f16(sacc[2*np+1], aM, bh4[2], bh4[3]);
            }
        }

        // ---- mask add (direct LDG, post-MMA), tile row max ----
        float tm0 = -INFINITY, tm1 = -INFINITY;
        #pragma unroll
        for (int nt = 0; nt < 8; ++nt) {
            float2 mk0 = *(const float2*)(mrow0 + t0 + nt * 8 + qc);
            float2 mk1 = *(const float2*)(mrow1 + t0 + nt * 8 + qc);
            sacc[nt][0] = fmaf(mk0.x, LOG2E, sacc[nt][0]);
            sacc[nt][1] = fmaf(mk0.y, LOG2E, sacc[nt][1]);
            sacc[nt][2] = fmaf(mk1.x, LOG2E, sacc[nt][2]);
            sacc[nt][3] = fmaf(mk1.y, LOG2E, sacc[nt][3]);
            tm0 = fmaxf(tm0, fmaxf(sacc[nt][0], sacc[nt][1]));
            tm1 = fmaxf(tm1, fmaxf(sacc[nt][2], sacc[nt][3]));
        }
        tm0 = fmaxf(tm0, __shfl_xor_sync(0xffffffffu, tm0, 1));
        tm0 = fmaxf(tm0, __shfl_xor_sync(0xffffffffu, tm0, 2));
        tm1 = fmaxf(tm1, __shfl_xor_sync(0xffffffffu, tm1, 1));
        tm1 = fmaxf(tm1, __shfl_xor_sync(0xffffffffu, tm1, 2));
        const float mn0 = fmaxf(m0, tm0), mn1 = fmaxf(m1, tm1);
        const float f0 = exp2f(m0 - mn0), f1 = exp2f(m1 - mn1);
        m0 = mn0; m1 = mn1;

        // ---- exp2 + gated exact dropout ----
        float zs0 = 0.0f, zs1 = 0.0f;
        #pragma unroll
        for (int nt = 0; nt < 8; ++nt) {
            const uint32_t colb = (uint32_t)(t0 + nt * 8 + qc);
            #pragma unroll
            for (int j = 0; j < 2; ++j) {
                float p = exp2f(sacc[nt][j] - mn0);
                zs0 += p;
                if (p >= 1e-10f) {
                    uint32_t bits = threefry_bits_42(cb0 + colb + (uint32_t)j);
                    if (!(jax_uniform(bits) < 0.9f)) p = 0.0f;
                }
                sacc[nt][j] = p;
            }
            #pragma unroll
            for (int j = 0; j < 2; ++j) {
                float p = exp2f(sacc[nt][2 + j] - mn1);
                zs1 += p;
                if (p >= 1e-10f) {
                    uint32_t bits = threefry_bits_42(cb1 + colb + (uint32_t)j);
                    if (!(jax_uniform(bits) < 0.9f)) p = 0.0f;
                }
                sacc[nt][2 + j] = p;
            }
        }
        zs0 += __shfl_xor_sync(0xffffffffu, zs0, 1);
        zs0 += __shfl_xor_sync(0xffffffffu, zs0, 2);
        zs1 += __shfl_xor_sync(0xffffffffu, zs1, 1);
        zs1 += __shfl_xor_sync(0xffffffffu, zs1, 2);
        Z0 = Z0 * f0 + zs0;
        Z1 = Z1 * f1 + zs1;

        // ---- rescale O (skip when f == 1 for both halves) ----
        if (f0 != 1.0f || f1 != 1.0f) {
            #pragma unroll
            for (int d = 0; d < 8; ++d) {
                Oa[d][0] *= f0; Oa[d][1] *= f0;
                Oa[d][2] *= f1; Oa[d][3] *= f1;
            }
        }

        // ---- PV: fp16 2-level P from regs, V x4t from smem ----
        #pragma unroll
        for (int ks = 0; ks < 4; ++ks) {
            uint32_t AH[4], AL[4];
            #pragma unroll
            for (int half = 0; half < 2; ++half) {
                const int nt = 2 * ks + half;
                float pA = sacc[nt][0], pB = sacc[nt][1];
                float pC = sacc[nt][2], pD = sacc[nt][3];
                __half2 hAB = __floats2half2_rn(pA, pB);
                __half2 hCD = __floats2half2_rn(pC, pD);
                AH[half * 2 + 0] = *(uint32_t*)&hAB;
                AH[half * 2 + 1] = *(uint32_t*)&hCD;
                float lA = pA - __half2float(__low2half(hAB));
                float lB = pB - __half2float(__high2half(hAB));
                float lC = pC - __half2float(__low2half(hCD));
                float lD = pD - __half2float(__high2half(hCD));
                AL[half * 2 + 0] = packh2(lA, lB);
                AL[half * 2 + 1] = packh2(lC, lD);
            }
            const int vr = 16 * ks + (lane & 15);
            #pragma unroll
            for (int dp = 0; dp < 4; ++dp) {
                const int vc8 = 2 * dp + (lane >> 4);
                const uint32_t voff = (uint32_t)swb(vr, vc8);
                uint32_t vh4[4], vl4[4];
                ldsm_x4t(vh4[0], vh4[1], vh4[2], vh4[3], kb + 16384 + voff);
                ldsm_x4t(vl4[0], vl4[1], vl4[2], vl4[3], kb + 24576 + voff);
                mma_f16(Oa[2*dp],   AH, vh4[0], vh4[1]);
                mma_f16(Oa[2*dp],   AH, vl4[0], vl4[1]);
                mma_f16(Oa[2*dp],   AL, vh4[0], vh4[1]);
                mma_f16(Oa[2*dp+1], AH, vh4[2], vh4[3]);
                mma_f16(Oa[2*dp+1], AH, vl4[2], vl4[3]);
                mma_f16(Oa[2*dp+1], AL, vh4[2], vh4[3]);
            }
        }
        __syncthreads();
    }

    // ---- epilogue ----
    const float iz0 = 1.0f / (Z0 * 0.9f);
    const float iz1 = 1.0f / (Z1 * 0.9f);
    float* orow0 = out + (((size_t)bh * S_ + rg0) << 6);
    float* orow1 = out + (((size_t)bh * S_ + rg1) << 6);
    #pragma unroll
    for (int dt = 0; dt < 8; ++dt) {
        float2 w0 = make_float2(Oa[dt][0] * iz0, Oa[dt][1] * iz0);
        float2 w1 = make_float2(Oa[dt][2] * iz1, Oa[dt][3] * iz1);
        *(float2*)(orow0 + dt * 8 + qc) = w0;
        *(float2*)(orow1 + dt * 8 + qc) = w1;
    }
}

// ---------------------------------------------------------------------------
extern "C" void kernel_launch(void* const* d_in, const int* in_sizes, int n_in,
                              void* d_out, int out_size)
{
    const float* query     = (const float*)d_in[0];
    const float* key       = (const float*)d_in[1];
    const float* value     = (const float*)d_in[2];
    const float* attn_mask = (const float*)d_in[3];
    const float* inv_scale = (const float*)d_in[4];
    const float* Wq = (const float*)d_in[5];
    const float* bq = (const float*)d_in[6];
    const float* Wk = (const float*)d_in[7];
    const float* bk = (const float*)d_in[8];
    const float* Wv = (const float*)d_in[9];
    const float* bv = (const float*)d_in[10];
    float* out = (float*)d_out;

    dim3 pgrid(NTOK / 64, 3);
    proj_kernel<<<pgrid, 256>>>(query, key, value, Wq, Wk, Wv, bq, bk, bv,
                                inv_scale);

    cudaFuncSetAttribute(attn_kernel,
                         cudaFuncAttributeMaxDynamicSharedMemorySize, SMEM_TOT);
    dim3 grid(S_ / BM, H_, B_);
    attn_kernel<<<grid, 256, SMEM_TOT>>>(attn_mask, out);
}

// round 15
// speedup vs baseline: 1.1693x; 1.0884x over previous
#include <cuda_runtime.h>
#include <cuda_fp16.h>
#include <cstdint>
#include <math.h>

#define B_ 2
#define H_ 16
#define S_ 2048
#define E_ 64
#define NTOK (B_*S_*H_)
#define BM 128
#define BN 64
#define NT_ (S_/BN)
#define LOG2E 1.4426950408889634f

// fp16 split levels of projected Q,K,V in [B,H,S,E] layout (Q pre-scaled by 8*log2e)
__device__ __half g_q0[B_*H_*S_*E_];
__device__ __half g_q1[B_*H_*S_*E_];
__device__ __half g_k0[B_*H_*S_*E_];
__device__ __half g_k1[B_*H_*S_*E_];
__device__ __half g_v0[B_*H_*S_*E_];
__device__ __half g_v1[B_*H_*S_*E_];

// ---------------- helpers ----------------
__device__ __forceinline__ uint32_t smem_u32(const void* p) {
    uint32_t a;
    asm("{ .reg .u64 t; cvta.to.shared.u64 t, %1; cvt.u32.u64 %0, t; }" : "=r"(a) : "l"(p));
    return a;
}
__device__ __forceinline__ void cpasync16(uint32_t dst, const void* src) {
    asm volatile("cp.async.cg.shared.global [%0], [%1], 16;" :: "r"(dst), "l"(src));
}
#define CP_COMMIT() asm volatile("cp.async.commit_group;" ::: "memory")
#define CP_WAIT1()  asm volatile("cp.async.wait_group 1;" ::: "memory")
#define CP_WAIT0()  asm volatile("cp.async.wait_group 0;" ::: "memory")

__device__ __forceinline__ void ldsm_x4(uint32_t& r0, uint32_t& r1, uint32_t& r2,
                                        uint32_t& r3, uint32_t a) {
    asm volatile("ldmatrix.sync.aligned.m8n8.x4.shared.b16 {%0,%1,%2,%3}, [%4];"
                 : "=r"(r0), "=r"(r1), "=r"(r2), "=r"(r3) : "r"(a));
}
__device__ __forceinline__ void ldsm_x4t(uint32_t& r0, uint32_t& r1, uint32_t& r2,
                                         uint32_t& r3, uint32_t a) {
    asm volatile("ldmatrix.sync.aligned.m8n8.x4.trans.shared.b16 {%0,%1,%2,%3}, [%4];"
                 : "=r"(r0), "=r"(r1), "=r"(r2), "=r"(r3) : "r"(a));
}
__device__ __forceinline__ void mma_f16(float* c, const uint32_t* a,
                                        uint32_t b0, uint32_t b1) {
    asm volatile("mma.sync.aligned.m16n8k16.row.col.f32.f16.f16.f32 "
                 "{%0,%1,%2,%3}, {%4,%5,%6,%7}, {%8,%9}, {%0,%1,%2,%3};"
                 : "+f"(c[0]), "+f"(c[1]), "+f"(c[2]), "+f"(c[3])
                 : "r"(a[0]), "r"(a[1]), "r"(a[2]), "r"(a[3]), "r"(b0), "r"(b1));
}

// ---------------- exact JAX threefry, key=(0,42), partitionable ----------------
__device__ __forceinline__ uint32_t threefry_bits_42(uint32_t c1) {
    const uint32_t ks1 = 42u, ks2 = 0x1BD11BDAu ^ 42u;
    uint32_t x0 = 0u, x1 = c1 + ks1;
#define TF_R(r) { x0 += x1; x1 = __funnelshift_l(x1, x1, (r)); x1 ^= x0; }
    TF_R(13) TF_R(15) TF_R(26) TF_R(6)
    x0 += ks1; x1 += ks2 + 1u;
    TF_R(17) TF_R(29) TF_R(16) TF_R(24)
    x0 += ks2; x1 += 2u;
    TF_R(13) TF_R(15) TF_R(26) TF_R(6)
    x1 += ks1 + 3u;
    TF_R(17) TF_R(29) TF_R(16) TF_R(24)
    x0 += ks1; x1 += ks2 + 4u;
    TF_R(13) TF_R(15) TF_R(26) TF_R(6)
    x0 += ks2; x1 += 5u;
#undef TF_R
    return x0 ^ x1;
}
__device__ __forceinline__ float jax_uniform(uint32_t bits) {
    return __uint_as_float((bits >> 9) | 0x3f800000u) - 1.0f;
}

// ---------------- fused projection (grid.y selects q/k/v), fp16 2-level split ----
__global__ __launch_bounds__(256) void proj_kernel(
    const float* __restrict__ xq, const float* __restrict__ xk,
    const float* __restrict__ xv,
    const float* __restrict__ Wq, const float* __restrict__ Wk,
    const float* __restrict__ Wv,
    const float* __restrict__ bq, const float* __restrict__ bk,
    const float* __restrict__ bv,
    const float* __restrict__ inv_scale)
{
    __shared__ float Xs[64][65];
    __shared__ float Ws[64][65];
    __shared__ float bs[64];
    const int which = blockIdx.y;
    const float* x = (which == 0) ? xq : (which == 1) ? xk : xv;
    const float* W = (which == 0) ? Wq : (which == 1) ? Wk : Wv;
    const float* bias = (which == 0) ? bq : (which == 1) ? bk : bv;
    __half* o0 = (which == 0) ? g_q0 : (which == 1) ? g_k0 : g_v0;
    __half* o1 = (which == 0) ? g_q1 : (which == 1) ? g_k1 : g_v1;
    // Q pre-scaled so QK^T emerges in log2 domain: q *= log2e / inv_scale
    const float scl = (which == 0) ? (LOG2E / inv_scale[0]) : 1.0f;

    const int tid = threadIdx.x;
    const int n0  = blockIdx.x * 64;
    #pragma unroll
    for (int it = 0; it < 4; ++it) {
        int elem = tid * 4 + it * 1024;
        int r = elem >> 6, c = elem & 63;
        float4 w4 = *(const float4*)(W + elem);
        Ws[r][c] = w4.x; Ws[r][c+1] = w4.y; Ws[r][c+2] = w4.z; Ws[r][c+3] = w4.w;
        float4 x4 = *(const float4*)(x + (size_t)n0 * 64 + elem);
        Xs[r][c] = x4.x; Xs[r][c+1] = x4.y; Xs[r][c+2] = x4.z; Xs[r][c+3] = x4.w;
    }
    if (tid < 64) bs[tid] = bias[tid];
    __syncthreads();
    const int tx = tid & 15, ty = tid >> 4;
    float acc[4][4] = {};
    #pragma unroll 8
    for (int d = 0; d < 64; ++d) {
        float a[4], b[4];
        #pragma unroll
        for (int i = 0; i < 4; ++i) a[i] = Xs[ty*4+i][d];
        #pragma unroll
        for (int j = 0; j < 4; ++j) b[j] = Ws[tx*4+j][d];
        #pragma unroll
        for (int i = 0; i < 4; ++i)
            #pragma unroll
            for (int j = 0; j < 4; ++j)
                acc[i][j] = fmaf(a[i], b[j], acc[i][j]);
    }
    #pragma unroll
    for (int i = 0; i < 4; ++i) {
        int n = n0 + ty*4 + i;
        int b_ = n >> 15, rem = n & 32767, s = rem >> 4, h = n & 15;
        size_t off = ((((size_t)b_ * H_ + h) * S_ + s) << 6);
        #pragma unroll
        for (int j = 0; j < 4; ++j) {
            int e = tx*4 + j;
            float v = (acc[i][j] + bs[e]) * scl;
            __half h0 = __float2half_rn(v);
            o0[off + e] = h0;
            o1[off + e] = __float2half_rn(v - __half2float(h0));
        }
    }
}

// ---------------- mma.sync fp16 flash attention, cp.async pipelined ----------------
#define SQ0 0
#define SQ1 16384
#define SKV 32768
#define KVB 32768
#define SMEM_TOT 98304
__device__ __forceinline__ int swb(int r, int c8) {
    return r * 128 + ((c8 ^ (r & 7)) << 4);
}

__global__ __launch_bounds__(256, 2) void attn_kernel(
    const float* __restrict__ mask,
    float* __restrict__ out)
{
    extern __shared__ char smem[];
    const uint32_t sb = smem_u32(smem);
    const int tid = threadIdx.x, warp = tid >> 5, lane = tid & 31;
    const int s0 = blockIdx.x * BM, h = blockIdx.y, b = blockIdx.z;
    const int bh = b * H_ + h;
    const size_t kplane = (size_t)bh * S_;

    // prologue: stage Q (2 levels) + KV tile 0 via cp.async
    const size_t qrow = (size_t)bh * S_ + s0;
    for (int c = tid; c < 128 * 8; c += 256) {
        int r = c >> 3, c8 = c & 7;
        size_t ge = ((qrow + r) << 6) + (c8 << 3);
        int so = swb(r, c8);
        cpasync16(sb + SQ0 + so, g_q0 + ge);
        cpasync16(sb + SQ1 + so, g_q1 + ge);
    }
    for (int c = tid; c < 64 * 8; c += 256) {
        int r = c >> 3, c8 = c & 7;
        size_t ge = ((kplane + r) << 6) + (c8 << 3);
        int so = swb(r, c8);
        cpasync16(sb + SKV + 0     + so, g_k0 + ge);
        cpasync16(sb + SKV + 8192  + so, g_k1 + ge);
        cpasync16(sb + SKV + 16384 + so, g_v0 + ge);
        cpasync16(sb + SKV + 24576 + so, g_v1 + ge);
    }
    CP_COMMIT();

    const int qr = lane >> 2;
    const int qc = (lane & 3) << 1;
    const int rg0 = s0 + warp * 16 + qr;
    const int rg1 = rg0 + 8;
    const float* mrow0 = mask + ((size_t)b * S_ + rg0) * S_;
    const float* mrow1 = mask + ((size_t)b * S_ + rg1) * S_;
    const uint32_t cb0 = ((uint32_t)bh * S_ + (uint32_t)rg0) * S_;
    const uint32_t cb1 = ((uint32_t)bh * S_ + (uint32_t)rg1) * S_;

    float m0 = -INFINITY, m1 = -INFINITY;
    float Z0 = 0.0f, Z1 = 0.0f;          // per-lane partials; reduced at epilogue
    float Oa[8][4];
    #pragma unroll
    for (int d = 0; d < 8; ++d)
        #pragma unroll
        for (int j = 0; j < 4; ++j) Oa[d][j] = 0.0f;

    for (int it = 0; it < NT_; ++it) {
        const int t0 = it * BN;
        if (it + 1 < NT_) {
            const uint32_t nb = sb + SKV + (uint32_t)(((it + 1) & 1) * KVB);
            const size_t koff = kplane + (size_t)(t0 + BN);
            for (int c = tid; c < 64 * 8; c += 256) {
                int r = c >> 3, c8 = c & 7;
                size_t ge = ((koff + r) << 6) + (c8 << 3);
                int so = swb(r, c8);
                cpasync16(nb + 0     + so, g_k0 + ge);
                cpasync16(nb + 8192  + so, g_k1 + ge);
                cpasync16(nb + 16384 + so, g_v0 + ge);
                cpasync16(nb + 24576 + so, g_v1 + ge);
            }
            CP_COMMIT();
            CP_WAIT1();
        } else {
            CP_WAIT0();
        }
        __syncthreads();
        const uint32_t kb = sb + SKV + (uint32_t)((it & 1) * KVB);

        // ---- QK^T: fp16 2-level, 3 terms; Q pre-scaled -> log2-domain scores ----
        float sacc[8][4];
        #pragma unroll
        for (int nt = 0; nt < 8; ++nt)
            #pragma unroll
            for (int j = 0; j < 4; ++j) sacc[nt][j] = 0.0f;

        #pragma unroll
        for (int ks = 0; ks < 4; ++ks) {
            const int lr  = warp * 16 + (lane & 7) + ((lane >> 3) & 1) * 8;
            const int lc8 = 2 * ks + (lane >> 4);
            const uint32_t aoff = (uint32_t)swb(lr, lc8);
            uint32_t aH[4], aM[4];
            ldsm_x4(aH[0], aH[1], aH[2], aH[3], sb + SQ0 + aoff);
            ldsm_x4(aM[0], aM[1], aM[2], aM[3], sb + SQ1 + aoff);
            const int br  = (lane & 7) + ((lane >> 4) << 3);
            const int bc8 = 2 * ks + ((lane >> 3) & 1);
            #pragma unroll
            for (int np = 0; np < 4; ++np) {
                const uint32_t boff = (uint32_t)swb(np * 16 + br, bc8);
                uint32_t bh4[4], bm4[4];
                ldsm_x4(bh4[0], bh4[1], bh4[2], bh4[3], kb + boff);
                ldsm_x4(bm4[0], bm4[1], bm4[2], bm4[3], kb + 8192 + boff);
                mma_f16(sacc[2*np],   aH, bh4[0], bh4[1]);
                mma_f16(sacc[2*np],   aH, bm4[0], bm4[1]);
                mma_f16(sacc[2*np],   aM, bh4[0], bh4[1]);
                mma_f16(sacc[2*np+1], aH, bh4[2], bh4[3]);
                mma_f16(sacc[2*np+1], aH, bm4[2], bm4[3]);
                mma_f16(sacc[2*np+1], aM, bh4[2], bh4[3]);
            }
        }

        // ---- mask add (direct LDG, post-MMA), tile row max ----
        float tm0 = -INFINITY, tm1 = -INFINITY;
        #pragma unroll
        for (int nt = 0; nt < 8; ++nt) {
            float2 mk0 = *(const float2*)(mrow0 + t0 + nt * 8 + qc);
            float2 mk1 = *(const float2*)(mrow1 + t0 + nt * 8 + qc);
            sacc[nt][0] = fmaf(mk0.x, LOG2E, sacc[nt][0]);
            sacc[nt][1] = fmaf(mk0.y, LOG2E, sacc[nt][1]);
            sacc[nt][2] = fmaf(mk1.x, LOG2E, sacc[nt][2]);
            sacc[nt][3] = fmaf(mk1.y, LOG2E, sacc[nt][3]);
            tm0 = fmaxf(tm0, fmaxf(sacc[nt][0], sacc[nt][1]));
            tm1 = fmaxf(tm1, fmaxf(sacc[nt][2], sacc[nt][3]));
        }
        tm0 = fmaxf(tm0, __shfl_xor_sync(0xffffffffu, tm0, 1));
        tm0 = fmaxf(tm0, __shfl_xor_sync(0xffffffffu, tm0, 2));
        tm1 = fmaxf(tm1, __shfl_xor_sync(0xffffffffu, tm1, 1));
        tm1 = fmaxf(tm1, __shfl_xor_sync(0xffffffffu, tm1, 2));
        const float mn0 = fmaxf(m0, tm0), mn1 = fmaxf(m1, tm1);
        const float f0 = exp2f(m0 - mn0), f1 = exp2f(m1 - mn1);
        m0 = mn0; m1 = mn1;

        // ---- exp2 + gated exact dropout (Z kept as per-lane partials) ----
        float zs0 = 0.0f, zs1 = 0.0f;
        #pragma unroll
        for (int nt = 0; nt < 8; ++nt) {
            const uint32_t colb = (uint32_t)(t0 + nt * 8 + qc);
            #pragma unroll
            for (int j = 0; j < 2; ++j) {
                float p = exp2f(sacc[nt][j] - mn0);
                zs0 += p;
                if (p >= 1e-10f) {
                    uint32_t bits = threefry_bits_42(cb0 + colb + (uint32_t)j);
                    if (!(jax_uniform(bits) < 0.9f)) p = 0.0f;
                }
                sacc[nt][j] = p;
            }
            #pragma unroll
            for (int j = 0; j < 2; ++j) {
                float p = exp2f(sacc[nt][2 + j] - mn1);
                zs1 += p;
                if (p >= 1e-10f) {
                    uint32_t bits = threefry_bits_42(cb1 + colb + (uint32_t)j);
                    if (!(jax_uniform(bits) < 0.9f)) p = 0.0f;
                }
                sacc[nt][2 + j] = p;
            }
        }
        Z0 = Z0 * f0 + zs0;
        Z1 = Z1 * f1 + zs1;

        // ---- rescale O (skip when f == 1 for both halves) ----
        if (f0 != 1.0f || f1 != 1.0f) {
            #pragma unroll
            for (int d = 0; d < 8; ++d) {
                Oa[d][0] *= f0; Oa[d][1] *= f0;
                Oa[d][2] *= f1; Oa[d][3] *= f1;
            }
        }

        // ---- PV: single-level fp16 P from regs, V 2-level x4t from smem ----
        #pragma unroll
        for (int ks = 0; ks < 4; ++ks) {
            uint32_t AH[4];
            #pragma unroll
            for (int half = 0; half < 2; ++half) {
                const int nt = 2 * ks + half;
                __half2 hAB = __floats2half2_rn(sacc[nt][0], sacc[nt][1]);
                __half2 hCD = __floats2half2_rn(sacc[nt][2], sacc[nt][3]);
                AH[half * 2 + 0] = *(uint32_t*)&hAB;
                AH[half * 2 + 1] = *(uint32_t*)&hCD;
            }
            const int vr = 16 * ks + (lane & 15);
            #pragma unroll
            for (int dp = 0; dp < 4; ++dp) {
                const int vc8 = 2 * dp + (lane >> 4);
                const uint32_t voff = (uint32_t)swb(vr, vc8);
                uint32_t vh4[4], vl4[4];
                ldsm_x4t(vh4[0], vh4[1], vh4[2], vh4[3], kb + 16384 + voff);
                ldsm_x4t(vl4[0], vl4[1], vl4[2], vl4[3], kb + 24576 + voff);
                mma_f16(Oa[2*dp],   AH, vh4[0], vh4[1]);
                mma_f16(Oa[2*dp],   AH, vl4[0], vl4[1]);
                mma_f16(Oa[2*dp+1], AH, vh4[2], vh4[3]);
                mma_f16(Oa[2*dp+1], AH, vl4[2], vl4[3]);
            }
        }
        __syncthreads();
    }

    // ---- epilogue: reduce Z partials across the quad, normalize, store ----
    Z0 += __shfl_xor_sync(0xffffffffu, Z0, 1);
    Z0 += __shfl_xor_sync(0xffffffffu, Z0, 2);
    Z1 += __shfl_xor_sync(0xffffffffu, Z1, 1);
    Z1 += __shfl_xor_sync(0xffffffffu, Z1, 2);
    const float iz0 = 1.0f / (Z0 * 0.9f);
    const float iz1 = 1.0f / (Z1 * 0.9f);
    float* orow0 = out + (((size_t)bh * S_ + rg0) << 6);
    float* orow1 = out + (((size_t)bh * S_ + rg1) << 6);
    #pragma unroll
    for (int dt = 0; dt < 8; ++dt) {
        float2 w0 = make_float2(Oa[dt][0] * iz0, Oa[dt][1] * iz0);
        float2 w1 = make_float2(Oa[dt][2] * iz1, Oa[dt][3] * iz1);
        *(float2*)(orow0 + dt * 8 + qc) = w0;
        *(float2*)(orow1 + dt * 8 + qc) = w1;
    }
}

// ---------------------------------------------------------------------------
extern "C" void kernel_launch(void* const* d_in, const int* in_sizes, int n_in,
                              void* d_out, int out_size)
{
    const float* query     = (const float*)d_in[0];
    const float* key       = (const float*)d_in[1];
    const float* value     = (const float*)d_in[2];
    const float* attn_mask = (const float*)d_in[3];
    const float* inv_scale = (const float*)d_in[4];
    const float* Wq = (const float*)d_in[5];
    const float* bq = (const float*)d_in[6];
    const float* Wk = (const float*)d_in[7];
    const float* bk = (const float*)d_in[8];
    const float* Wv = (const float*)d_in[9];
    const float* bv = (const float*)d_in[10];
    float* out = (float*)d_out;

    dim3 pgrid(NTOK / 64, 3);
    proj_kernel<<<pgrid, 256>>>(query, key, value, Wq, Wk, Wv, bq, bk, bv,
                                inv_scale);

    cudaFuncSetAttribute(attn_kernel,
                         cudaFuncAttributeMaxDynamicSharedMemorySize, SMEM_TOT);
    dim3 grid(S_ / BM, H_, B_);
    attn_kernel<<<grid, 256, SMEM_TOT>>>(attn_mask, out);
}

// round 16
// speedup vs baseline: 1.2402x; 1.0606x over previous
#include <cuda_runtime.h>
#include <cuda_fp16.h>
#include <cstdint>
#include <math.h>

#define B_ 2
#define H_ 16
#define S_ 2048
#define E_ 64
#define NTOK (B_*S_*H_)
#define BM 128
#define BN 64
#define NT_ (S_/BN)
#define LOG2E 1.4426950408889634f

// fp16 split levels of projected Q,K (2-level) and V (single-level used)
__device__ __half g_q0[B_*H_*S_*E_];
__device__ __half g_q1[B_*H_*S_*E_];
__device__ __half g_k0[B_*H_*S_*E_];
__device__ __half g_k1[B_*H_*S_*E_];
__device__ __half g_v0[B_*H_*S_*E_];
__device__ __half g_v1[B_*H_*S_*E_];   // written by proj, unused by attn

// ---------------- helpers ----------------
__device__ __forceinline__ uint32_t smem_u32(const void* p) {
    uint32_t a;
    asm("{ .reg .u64 t; cvta.to.shared.u64 t, %1; cvt.u32.u64 %0, t; }" : "=r"(a) : "l"(p));
    return a;
}
__device__ __forceinline__ void cpasync16(uint32_t dst, const void* src) {
    asm volatile("cp.async.cg.shared.global [%0], [%1], 16;" :: "r"(dst), "l"(src));
}
#define CP_COMMIT() asm volatile("cp.async.commit_group;" ::: "memory")
#define CP_WAIT1()  asm volatile("cp.async.wait_group 1;" ::: "memory")
#define CP_WAIT0()  asm volatile("cp.async.wait_group 0;" ::: "memory")

__device__ __forceinline__ void ldsm_x4(uint32_t& r0, uint32_t& r1, uint32_t& r2,
                                        uint32_t& r3, uint32_t a) {
    asm volatile("ldmatrix.sync.aligned.m8n8.x4.shared.b16 {%0,%1,%2,%3}, [%4];"
                 : "=r"(r0), "=r"(r1), "=r"(r2), "=r"(r3) : "r"(a));
}
__device__ __forceinline__ void ldsm_x4t(uint32_t& r0, uint32_t& r1, uint32_t& r2,
                                         uint32_t& r3, uint32_t a) {
    asm volatile("ldmatrix.sync.aligned.m8n8.x4.trans.shared.b16 {%0,%1,%2,%3}, [%4];"
                 : "=r"(r0), "=r"(r1), "=r"(r2), "=r"(r3) : "r"(a));
}
__device__ __forceinline__ void mma_f16(float* c, const uint32_t* a,
                                        uint32_t b0, uint32_t b1) {
    asm volatile("mma.sync.aligned.m16n8k16.row.col.f32.f16.f16.f32 "
                 "{%0,%1,%2,%3}, {%4,%5,%6,%7}, {%8,%9}, {%0,%1,%2,%3};"
                 : "+f"(c[0]), "+f"(c[1]), "+f"(c[2]), "+f"(c[3])
                 : "r"(a[0]), "r"(a[1]), "r"(a[2]), "r"(a[3]), "r"(b0), "r"(b1));
}

// ---------------- exact JAX threefry, key=(0,42), partitionable ----------------
__device__ __forceinline__ uint32_t threefry_bits_42(uint32_t c1) {
    const uint32_t ks1 = 42u, ks2 = 0x1BD11BDAu ^ 42u;
    uint32_t x0 = 0u, x1 = c1 + ks1;
#define TF_R(r) { x0 += x1; x1 = __funnelshift_l(x1, x1, (r)); x1 ^= x0; }
    TF_R(13) TF_R(15) TF_R(26) TF_R(6)
    x0 += ks1; x1 += ks2 + 1u;
    TF_R(17) TF_R(29) TF_R(16) TF_R(24)
    x0 += ks2; x1 += 2u;
    TF_R(13) TF_R(15) TF_R(26) TF_R(6)
    x1 += ks1 + 3u;
    TF_R(17) TF_R(29) TF_R(16) TF_R(24)
    x0 += ks1; x1 += ks2 + 4u;
    TF_R(13) TF_R(15) TF_R(26) TF_R(6)
    x0 += ks2; x1 += 5u;
#undef TF_R
    return x0 ^ x1;
}
__device__ __forceinline__ float jax_uniform(uint32_t bits) {
    return __uint_as_float((bits >> 9) | 0x3f800000u) - 1.0f;
}

// ---------------- fused projection (grid.y selects q/k/v), fp16 2-level split ----
__global__ __launch_bounds__(256) void proj_kernel(
    const float* __restrict__ xq, const float* __restrict__ xk,
    const float* __restrict__ xv,
    const float* __restrict__ Wq, const float* __restrict__ Wk,
    const float* __restrict__ Wv,
    const float* __restrict__ bq, const float* __restrict__ bk,
    const float* __restrict__ bv,
    const float* __restrict__ inv_scale)
{
    __shared__ float Xs[64][65];
    __shared__ float Ws[64][65];
    __shared__ float bs[64];
    const int which = blockIdx.y;
    const float* x = (which == 0) ? xq : (which == 1) ? xk : xv;
    const float* W = (which == 0) ? Wq : (which == 1) ? Wk : Wv;
    const float* bias = (which == 0) ? bq : (which == 1) ? bk : bv;
    __half* o0 = (which == 0) ? g_q0 : (which == 1) ? g_k0 : g_v0;
    __half* o1 = (which == 0) ? g_q1 : (which == 1) ? g_k1 : g_v1;
    // Q pre-scaled so QK^T emerges in log2 domain: q *= log2e / inv_scale
    const float scl = (which == 0) ? (LOG2E / inv_scale[0]) : 1.0f;

    const int tid = threadIdx.x;
    const int n0  = blockIdx.x * 64;
    #pragma unroll
    for (int it = 0; it < 4; ++it) {
        int elem = tid * 4 + it * 1024;
        int r = elem >> 6, c = elem & 63;
        float4 w4 = *(const float4*)(W + elem);
        Ws[r][c] = w4.x; Ws[r][c+1] = w4.y; Ws[r][c+2] = w4.z; Ws[r][c+3] = w4.w;
        float4 x4 = *(const float4*)(x + (size_t)n0 * 64 + elem);
        Xs[r][c] = x4.x; Xs[r][c+1] = x4.y; Xs[r][c+2] = x4.z; Xs[r][c+3] = x4.w;
    }
    if (tid < 64) bs[tid] = bias[tid];
    __syncthreads();
    const int tx = tid & 15, ty = tid >> 4;
    float acc[4][4] = {};
    #pragma unroll 8
    for (int d = 0; d < 64; ++d) {
        float a[4], b[4];
        #pragma unroll
        for (int i = 0; i < 4; ++i) a[i] = Xs[ty*4+i][d];
        #pragma unroll
        for (int j = 0; j < 4; ++j) b[j] = Ws[tx*4+j][d];
        #pragma unroll
        for (int i = 0; i < 4; ++i)
            #pragma unroll
            for (int j = 0; j < 4; ++j)
                acc[i][j] = fmaf(a[i], b[j], acc[i][j]);
    }
    #pragma unroll
    for (int i = 0; i < 4; ++i) {
        int n = n0 + ty*4 + i;
        int b_ = n >> 15, rem = n & 32767, s = rem >> 4, h = n & 15;
        size_t off = ((((size_t)b_ * H_ + h) * S_ + s) << 6);
        #pragma unroll
        for (int j = 0; j < 4; ++j) {
            int e = tx*4 + j;
            float v = (acc[i][j] + bs[e]) * scl;
            __half h0 = __float2half_rn(v);
            o0[off + e] = h0;
            o1[off + e] = __float2half_rn(v - __half2float(h0));
        }
    }
}

// ---------------- mma.sync fp16 flash attention, cp.async pipelined ----------------
// smem: Q (2 levels, 32KB) + double-buffered K0/K1/V0 (2 x 24KB) = 80KB
#define SQ0 0
#define SQ1 16384
#define SKV 32768
#define KVB 24576
#define SMEM_TOT 81920
__device__ __forceinline__ int swb(int r, int c8) {
    return r * 128 + ((c8 ^ (r & 7)) << 4);
}

__global__ __launch_bounds__(256, 2) void attn_kernel(
    const float* __restrict__ mask,
    float* __restrict__ out)
{
    extern __shared__ char smem[];
    const uint32_t sb = smem_u32(smem);
    const int tid = threadIdx.x, warp = tid >> 5, lane = tid & 31;
    const int s0 = blockIdx.x * BM, h = blockIdx.y, b = blockIdx.z;
    const int bh = b * H_ + h;
    const size_t kplane = (size_t)bh * S_;

    // prologue: stage Q (2 levels) + KV tile 0 via cp.async
    const size_t qrow = (size_t)bh * S_ + s0;
    for (int c = tid; c < 128 * 8; c += 256) {
        int r = c >> 3, c8 = c & 7;
        size_t ge = ((qrow + r) << 6) + (c8 << 3);
        int so = swb(r, c8);
        cpasync16(sb + SQ0 + so, g_q0 + ge);
        cpasync16(sb + SQ1 + so, g_q1 + ge);
    }
    for (int c = tid; c < 64 * 8; c += 256) {
        int r = c >> 3, c8 = c & 7;
        size_t ge = ((kplane + r) << 6) + (c8 << 3);
        int so = swb(r, c8);
        cpasync16(sb + SKV + 0     + so, g_k0 + ge);
        cpasync16(sb + SKV + 8192  + so, g_k1 + ge);
        cpasync16(sb + SKV + 16384 + so, g_v0 + ge);
    }
    CP_COMMIT();

    const int qr = lane >> 2;
    const int qc = (lane & 3) << 1;
    const int rg0 = s0 + warp * 16 + qr;
    const int rg1 = rg0 + 8;
    const float* mrow0 = mask + ((size_t)b * S_ + rg0) * S_;
    const float* mrow1 = mask + ((size_t)b * S_ + rg1) * S_;
    const uint32_t cb0 = ((uint32_t)bh * S_ + (uint32_t)rg0) * S_;
    const uint32_t cb1 = ((uint32_t)bh * S_ + (uint32_t)rg1) * S_;

    float m0 = -INFINITY, m1 = -INFINITY;
    float Z0 = 0.0f, Z1 = 0.0f;          // per-lane partials; reduced at epilogue
    float Oa[8][4];
    #pragma unroll
    for (int d = 0; d < 8; ++d)
        #pragma unroll
        for (int j = 0; j < 4; ++j) Oa[d][j] = 0.0f;

    for (int it = 0; it < NT_; ++it) {
        const int t0 = it * BN;
        if (it + 1 < NT_) {
            const uint32_t nb = sb + SKV + (uint32_t)(((it + 1) & 1) * KVB);
            const size_t koff = kplane + (size_t)(t0 + BN);
            for (int c = tid; c < 64 * 8; c += 256) {
                int r = c >> 3, c8 = c & 7;
                size_t ge = ((koff + r) << 6) + (c8 << 3);
                int so = swb(r, c8);
                cpasync16(nb + 0     + so, g_k0 + ge);
                cpasync16(nb + 8192  + so, g_k1 + ge);
                cpasync16(nb + 16384 + so, g_v0 + ge);
            }
            CP_COMMIT();
            CP_WAIT1();
        } else {
            CP_WAIT0();
        }
        __syncthreads();
        const uint32_t kb = sb + SKV + (uint32_t)((it & 1) * KVB);

        // ---- QK^T: fp16 2-level, 3 terms; Q pre-scaled -> log2-domain scores ----
        float sacc[8][4];
        #pragma unroll
        for (int nt = 0; nt < 8; ++nt)
            #pragma unroll
            for (int j = 0; j < 4; ++j) sacc[nt][j] = 0.0f;

        #pragma unroll
        for (int ks = 0; ks < 4; ++ks) {
            const int lr  = warp * 16 + (lane & 7) + ((lane >> 3) & 1) * 8;
            const int lc8 = 2 * ks + (lane >> 4);
            const uint32_t aoff = (uint32_t)swb(lr, lc8);
            uint32_t aH[4], aM[4];
            ldsm_x4(aH[0], aH[1], aH[2], aH[3], sb + SQ0 + aoff);
            ldsm_x4(aM[0], aM[1], aM[2], aM[3], sb + SQ1 + aoff);
            const int br  = (lane & 7) + ((lane >> 4) << 3);
            const int bc8 = 2 * ks + ((lane >> 3) & 1);
            #pragma unroll
            for (int np = 0; np < 4; ++np) {
                const uint32_t boff = (uint32_t)swb(np * 16 + br, bc8);
                uint32_t bh4[4], bm4[4];
                ldsm_x4(bh4[0], bh4[1], bh4[2], bh4[3], kb + boff);
                ldsm_x4(bm4[0], bm4[1], bm4[2], bm4[3], kb + 8192 + boff);
                mma_f16(sacc[2*np],   aH, bh4[0], bh4[1]);
                mma_f16(sacc[2*np],   aH, bm4[0], bm4[1]);
                mma_f16(sacc[2*np],   aM, bh4[0], bh4[1]);
                mma_f16(sacc[2*np+1], aH, bh4[2], bh4[3]);
                mma_f16(sacc[2*np+1], aH, bm4[2], bm4[3]);
                mma_f16(sacc[2*np+1], aM, bh4[2], bh4[3]);
            }
        }

        // ---- mask add (direct LDG, post-MMA), tile row max ----
        float tm0 = -INFINITY, tm1 = -INFINITY;
        #pragma unroll
        for (int nt = 0; nt < 8; ++nt) {
            float2 mk0 = *(const float2*)(mrow0 + t0 + nt * 8 + qc);
            float2 mk1 = *(const float2*)(mrow1 + t0 + nt * 8 + qc);
            sacc[nt][0] = fmaf(mk0.x, LOG2E, sacc[nt][0]);
            sacc[nt][1] = fmaf(mk0.y, LOG2E, sacc[nt][1]);
            sacc[nt][2] = fmaf(mk1.x, LOG2E, sacc[nt][2]);
            sacc[nt][3] = fmaf(mk1.y, LOG2E, sacc[nt][3]);
            tm0 = fmaxf(tm0, fmaxf(sacc[nt][0], sacc[nt][1]));
            tm1 = fmaxf(tm1, fmaxf(sacc[nt][2], sacc[nt][3]));
        }
        tm0 = fmaxf(tm0, __shfl_xor_sync(0xffffffffu, tm0, 1));
        tm0 = fmaxf(tm0, __shfl_xor_sync(0xffffffffu, tm0, 2));
        tm1 = fmaxf(tm1, __shfl_xor_sync(0xffffffffu, tm1, 1));
        tm1 = fmaxf(tm1, __shfl_xor_sync(0xffffffffu, tm1, 2));
        const float mn0 = fmaxf(m0, tm0), mn1 = fmaxf(m1, tm1);
        const float f0 = exp2f(m0 - mn0), f1 = exp2f(m1 - mn1);
        m0 = mn0; m1 = mn1;

        // ---- exp2 + gated exact dropout (Z kept as per-lane partials) ----
        float zs0 = 0.0f, zs1 = 0.0f;
        #pragma unroll
        for (int nt = 0; nt < 8; ++nt) {
            const uint32_t colb = (uint32_t)(t0 + nt * 8 + qc);
            #pragma unroll
            for (int j = 0; j < 2; ++j) {
                float p = exp2f(sacc[nt][j] - mn0);
                zs0 += p;
                if (p >= 1e-10f) {
                    uint32_t bits = threefry_bits_42(cb0 + colb + (uint32_t)j);
                    if (!(jax_uniform(bits) < 0.9f)) p = 0.0f;
                }
                sacc[nt][j] = p;
            }
            #pragma unroll
            for (int j = 0; j < 2; ++j) {
                float p = exp2f(sacc[nt][2 + j] - mn1);
                zs1 += p;
                if (p >= 1e-10f) {
                    uint32_t bits = threefry_bits_42(cb1 + colb + (uint32_t)j);
                    if (!(jax_uniform(bits) < 0.9f)) p = 0.0f;
                }
                sacc[nt][2 + j] = p;
            }
        }
        Z0 = Z0 * f0 + zs0;
        Z1 = Z1 * f1 + zs1;

        // ---- rescale O (skip when f == 1 for both halves) ----
        if (f0 != 1.0f || f1 != 1.0f) {
            #pragma unroll
            for (int d = 0; d < 8; ++d) {
                Oa[d][0] *= f0; Oa[d][1] *= f0;
                Oa[d][2] *= f1; Oa[d][3] *= f1;
            }
        }

        // ---- PV: single-level fp16 P from regs, single-level V x4t from smem ----
        #pragma unroll
        for (int ks = 0; ks < 4; ++ks) {
            uint32_t AH[4];
            #pragma unroll
            for (int half = 0; half < 2; ++half) {
                const int nt = 2 * ks + half;
                __half2 hAB = __floats2half2_rn(sacc[nt][0], sacc[nt][1]);
                __half2 hCD = __floats2half2_rn(sacc[nt][2], sacc[nt][3]);
                AH[half * 2 + 0] = *(uint32_t*)&hAB;
                AH[half * 2 + 1] = *(uint32_t*)&hCD;
            }
            const int vr = 16 * ks + (lane & 15);
            #pragma unroll
            for (int dp = 0; dp < 4; ++dp) {
                const int vc8 = 2 * dp + (lane >> 4);
                const uint32_t voff = (uint32_t)swb(vr, vc8);
                uint32_t vh4[4];
                ldsm_x4t(vh4[0], vh4[1], vh4[2], vh4[3], kb + 16384 + voff);
                mma_f16(Oa[2*dp],   AH, vh4[0], vh4[1]);
                mma_f16(Oa[2*dp+1], AH, vh4[2], vh4[3]);
            }
        }
        __syncthreads();
    }

    // ---- epilogue: reduce Z partials across the quad, normalize, store ----
    Z0 += __shfl_xor_sync(0xffffffffu, Z0, 1);
    Z0 += __shfl_xor_sync(0xffffffffu, Z0, 2);
    Z1 += __shfl_xor_sync(0xffffffffu, Z1, 1);
    Z1 += __shfl_xor_sync(0xffffffffu, Z1, 2);
    const float iz0 = 1.0f / (Z0 * 0.9f);
    const float iz1 = 1.0f / (Z1 * 0.9f);
    float* orow0 = out + (((size_t)bh * S_ + rg0) << 6);
    float* orow1 = out + (((size_t)bh * S_ + rg1) << 6);
    #pragma unroll
    for (int dt = 0; dt < 8; ++dt) {
        float2 w0 = make_float2(Oa[dt][0] * iz0, Oa[dt][1] * iz0);
        float2 w1 = make_float2(Oa[dt][2] * iz1, Oa[dt][3] * iz1);
        *(float2*)(orow0 + dt * 8 + qc) = w0;
        *(float2*)(orow1 + dt * 8 + qc) = w1;
    }
}

// ---------------------------------------------------------------------------
extern "C" void kernel_launch(void* const* d_in, const int* in_sizes, int n_in,
                              void* d_out, int out_size)
{
    const float* query     = (const float*)d_in[0];
    const float* key       = (const float*)d_in[1];
    const float* value     = (const float*)d_in[2];
    const float* attn_mask = (const float*)d_in[3];
    const float* inv_scale = (const float*)d_in[4];
    const float* Wq = (const float*)d_in[5];
    const float* bq = (const float*)d_in[6];
    const float* Wk = (const float*)d_in[7];
    const float* bk = (const float*)d_in[8];
    const float* Wv = (const float*)d_in[9];
    const float* bv = (const float*)d_in[10];
    float* out = (float*)d_out;

    dim3 pgrid(NTOK / 64, 3);
    proj_kernel<<<pgrid, 256>>>(query, key, value, Wq, Wk, Wv, bq, bk, bv,
                                inv_scale);

    cudaFuncSetAttribute(attn_kernel,
                         cudaFuncAttributeMaxDynamicSharedMemorySize, SMEM_TOT);
    dim3 grid(S_ / BM, H_, B_);
    attn_kernel<<<grid, 256, SMEM_TOT>>>(attn_mask, out);
}